// round 12
// baseline (speedup 1.0000x reference)
#include <cuda_runtime.h>
#include <math.h>

#define BQ      256      // batch (queries)
#define D       512      // embedding dim
#define NTRAIN  50000    // train rows
#define NATTR   8        // attributes
#define CAP     1024     // per-b matched-sim buffer (mean ~130, huge margin)
#define KNB     5        // top-k
#define NBLK_M  592      // 4 blocks/SM x 148 SMs
#define RPB     85       // rows per block (592*85 = 50320 >= 50000)
#define PMAX    384      // block pair-list cap (mean ~56, +26 sigma margin)

// ---------------- device scratch (no allocations allowed) ----------------
// g_count zero at static init; tail re-zeroes after reading -> graph-replay-safe.
__device__ int                g_count[BQ];      // matched count per query
__device__ float              g_sims[BQ * CAP]; // matched (dot * inv_row) per query
__device__ unsigned long long g_done;           // monotonic completion counter (no reset)

// ---------------- single kernel: bit-sliced match + sparse dots + last-block topk ----
__global__ void __launch_bounds__(256) fused_kernel(const float* __restrict__ emb,
                                                    const int* __restrict__ attr,
                                                    const float* __restrict__ z,
                                                    const int* __restrict__ tattr,
                                                    float* __restrict__ out) {
    __shared__ unsigned       s_mask[NATTR * 3 * 8];  // [attr][val][word]: targets with attr==val
    __shared__ unsigned short s_pairs[PMAX];          // (row_local << 8) | b
    __shared__ int            s_np;
    __shared__ int            s_last;
    __shared__ float          s_part[8];

    int t = threadIdx.x, w = t >> 5, lane = t & 31;

    // ---- build value-indexed target bitmasks (one ballot set per warp) ----
    {
        int av[NATTR];
        const int* a = tattr + t * NATTR;
        #pragma unroll
        for (int i = 0; i < NATTR; i++) av[i] = a[i];
        #pragma unroll
        for (int ai = 0; ai < NATTR; ai++) {
            #pragma unroll
            for (int v = 0; v < 3; v++) {
                unsigned m = __ballot_sync(0xffffffffu, av[ai] == v);
                if (lane == 0) s_mask[(ai * 3 + v) * 8 + w] = m;
            }
        }
    }
    if (t == 0) s_np = 0;
    __syncthreads();

    int base = blockIdx.x * RPB;
    int q = lane >> 3, oct = lane & 7;      // lane -> (row-in-quad, target-word)

    // ---- phase A: each warp tests 4 rows per iteration (bit-sliced, no ballots) ----
    for (int r0 = w * 4; r0 < RPB; r0 += 32) {
        int rl = r0 + q;                    // row local to block
        int n = base + rl;
        bool rowok = (rl < RPB) && (n < NTRAIN);
        // coalesced 128B load: 4 rows x 8 attrs
        int val = rowok ? attr[(size_t)n * NATTR + oct] : 0;

        // pack row attrs within each octet (all 8 lanes of octet end with full p)
        unsigned p = ((unsigned)val & 3u) << (2 * oct);
        p |= __shfl_xor_sync(0xffffffffu, p, 1);
        p |= __shfl_xor_sync(0xffffffffu, p, 2);
        p |= __shfl_xor_sync(0xffffffffu, p, 4);

        // bit-sliced mismatch count over this lane's 32 targets
        unsigned seen = 0, two = 0;
        #pragma unroll
        for (int ai = 0; ai < NATTR; ai++) {
            unsigned v = (p >> (2 * ai)) & 3u;
            unsigned m = ~s_mask[(ai * 3 + v) * 8 + oct];   // mismatching targets
            two  |= seen & m;
            seen |= m;
        }
        unsigned hit = rowok ? ~two : 0u;   // <=1 mismatch <=> match_score >= 7

        // warp compaction of hit bits into the block pair list
        int c = __popc(hit);
        int pre = c;
        #pragma unroll
        for (int o = 1; o < 32; o <<= 1) {
            int u = __shfl_up_sync(0xffffffffu, pre, o);
            if (lane >= o) pre += u;
        }
        int tot = __shfl_sync(0xffffffffu, pre, 31);
        if (tot) {
            int bpos = 0;
            if (lane == 31) bpos = atomicAdd(&s_np, tot);
            bpos = __shfl_sync(0xffffffffu, bpos, 31);
            int idx = bpos + pre - c;
            unsigned rem = hit;
            while (rem) {
                int bit = __ffs(rem) - 1;
                rem &= rem - 1;
                if (idx < PMAX)
                    s_pairs[idx] = (unsigned short)((rl << 8) | (oct * 32 + bit));
                idx++;
            }
        }
    }
    __syncthreads();
    int np = s_np < PMAX ? s_np : PMAX;

    // ---- phase B: pairs distributed across all 8 warps (8 indep LDG.128 each) ----
    for (int j = w; j < np; j += 8) {
        int pr  = s_pairs[j];
        int row = base + (pr >> 8);
        int b   = pr & 255;

        const float4* rr = (const float4*)(emb + (size_t)row * D);
        const float4* zr = (const float4*)(z + (size_t)b * D);
        float4 r0 = rr[lane];      float4 z0 = zr[lane];
        float4 r1 = rr[lane + 32]; float4 z1 = zr[lane + 32];
        float4 r2 = rr[lane + 64]; float4 z2 = zr[lane + 64];
        float4 r3 = rr[lane + 96]; float4 z3 = zr[lane + 96];

        float ss = r0.x*r0.x + r0.y*r0.y + r0.z*r0.z + r0.w*r0.w
                 + r1.x*r1.x + r1.y*r1.y + r1.z*r1.z + r1.w*r1.w
                 + r2.x*r2.x + r2.y*r2.y + r2.z*r2.z + r2.w*r2.w
                 + r3.x*r3.x + r3.y*r3.y + r3.z*r3.z + r3.w*r3.w;
        float d  = r0.x*z0.x + r0.y*z0.y + r0.z*z0.z + r0.w*z0.w
                 + r1.x*z1.x + r1.y*z1.y + r1.z*z1.z + r1.w*z1.w
                 + r2.x*z2.x + r2.y*z2.y + r2.z*z2.z + r2.w*z2.w
                 + r3.x*z3.x + r3.y*z3.y + r3.z*z3.z + r3.w*z3.w;
        #pragma unroll
        for (int o = 16; o; o >>= 1) {
            ss += __shfl_xor_sync(0xffffffffu, ss, o);
            d  += __shfl_xor_sync(0xffffffffu, d,  o);
        }
        if (lane == 0) {
            float inv = 1.0f / fmaxf(sqrtf(ss), 1e-12f);  // row inv-norm (F.normalize eps)
            int pos = atomicAdd(&g_count[b], 1);
            if (pos < CAP) g_sims[(size_t)b * CAP + pos] = d * inv;
        }
    }

    // ---- completion: monotonic counter; exactly one block becomes the tail ----
    __syncthreads();
    if (t == 0) {
        __threadfence();                               // release sims/count writes
        unsigned long long my = atomicAdd(&g_done, 1ULL);
        s_last = ((my % NBLK_M) == NBLK_M - 1) ? 1 : 0;
    }
    __syncthreads();
    if (!s_last) return;
    __threadfence();                                    // acquire other blocks' writes

    // ---- tail: last block does top-5 for all 256 queries (warp-per-query) ----
    float wsum = 0.0f;                                  // warp w: queries w, w+8, ... (in order)
    for (int b = w; b < BQ; b += 8) {
        // inv-norm of z[b] (L2-hot); invz > 0 preserves top-k order, applied at end
        const float4* zr = (const float4*)(z + (size_t)b * D);
        float4 z0 = zr[lane], z1 = zr[lane + 32], z2 = zr[lane + 64], z3 = zr[lane + 96];
        float ss = z0.x*z0.x + z0.y*z0.y + z0.z*z0.z + z0.w*z0.w
                 + z1.x*z1.x + z1.y*z1.y + z1.z*z1.z + z1.w*z1.w
                 + z2.x*z2.x + z2.y*z2.y + z2.z*z2.z + z2.w*z2.w
                 + z3.x*z3.x + z3.y*z3.y + z3.z*z3.z + z3.w*z3.w;
        #pragma unroll
        for (int o = 16; o; o >>= 1) ss += __shfl_xor_sync(0xffffffffu, ss, o);
        float invz = 1.0f / fmaxf(sqrtf(ss), 1e-12f);

        int cnt = __ldcg(&g_count[b]);
        if (cnt > CAP) cnt = CAP;
        if (lane == 0) g_count[b] = 0;                 // reset for next graph replay

        // per-lane sorted top-5 registers over strided sims (bypass L1: other SMs wrote)
        float t0 = -1e30f, t1 = -1e30f, t2 = -1e30f, t3 = -1e30f, t4 = -1e30f;
        for (int i = lane; i < cnt; i += 32) {
            float v = __ldcg(&g_sims[(size_t)b * CAP + i]);
            if (v > t4) {
                if      (v > t0) { t4=t3; t3=t2; t2=t1; t1=t0; t0=v; }
                else if (v > t1) { t4=t3; t3=t2; t2=t1; t1=v; }
                else if (v > t2) { t4=t3; t3=t2; t2=v; }
                else if (v > t3) { t4=t3; t3=v; }
                else             { t4=v; }
            }
        }

        // 5 merge rounds; masked_sim has 49k+ zeros -> each selection clamps at 0
        float sum5 = 0.0f;
        #pragma unroll
        for (int k = 0; k < KNB; k++) {
            float m = t0;
            #pragma unroll
            for (int o = 16; o; o >>= 1) m = fmaxf(m, __shfl_xor_sync(0xffffffffu, m, o));
            sum5 += fmaxf(m, 0.0f);
            unsigned msk = __ballot_sync(0xffffffffu, t0 == m);
            int owner = (int)__ffs(msk) - 1;
            if (lane == owner) { t0=t1; t1=t2; t2=t3; t3=t4; t4=-1e30f; }
        }

        float per = 1.0f - (invz * sum5) / (float)KNB;
        wsum += (cnt >= KNB) ? per : 0.0f;             // fixed per-warp order
    }

    if (lane == 0) s_part[w] = wsum;
    __syncthreads();
    if (t == 0) {
        float s = 0.0f;
        #pragma unroll
        for (int i = 0; i < 8; i++) s += s_part[i];    // fixed order: deterministic
        out[0] = s / (float)BQ;
    }
}

extern "C" void kernel_launch(void* const* d_in, const int* in_sizes, int n_in,
                              void* d_out, int out_size) {
    const float* z     = (const float*)d_in[0];   // z_flowed         [256,512]   f32
    const int*   tattr = (const int*)d_in[1];     // target_attrs     [256,8]     i32
    const float* emb   = (const float*)d_in[2];   // train_embeddings [50000,512] f32
    const int*   attr  = (const int*)d_in[3];     // train_attributes [50000,8]   i32
    float*       out   = (float*)d_out;

    fused_kernel<<<NBLK_M, 256>>>(emb, attr, z, tattr, out);
}

// round 13
// speedup vs baseline: 2.8704x; 2.8704x over previous
#include <cuda_runtime.h>
#include <math.h>

#define BQ      256      // batch (queries)
#define D       512      // embedding dim
#define NTRAIN  50000    // train rows
#define NATTR   8        // attributes
#define CAP     1024     // per-b matched-sim buffer (mean ~130, huge margin)
#define KNB     5        // top-k
#define NBLK_M  592      // 4 blocks/SM x 148 SMs worth of blocks
#define RPB     85       // rows per block (592*85 = 50320 >= 50000)
#define PMAX    384      // block pair-list cap (mean ~56, +26 sigma margin)
#define TAILB   32       // tail blocks: 32 x 8 warps = 256 queries, one warp each

// ---------------- device scratch (no allocations allowed) ----------------
// g_count zero at static init; tail re-zeroes after reading -> graph-replay-safe.
__device__ int                g_count[BQ];      // matched count per query
__device__ float              g_sims[BQ * CAP]; // matched (dot * inv_row) per query
__device__ float              g_loss[BQ];       // per-query loss contribution
__device__ unsigned long long g_done;           // monotonic match-completion counter
__device__ unsigned long long g_done2;          // monotonic tail-completion counter

__global__ void __launch_bounds__(256, 3) fused_kernel(const float* __restrict__ emb,
                                                       const int* __restrict__ attr,
                                                       const float* __restrict__ z,
                                                       const int* __restrict__ tattr,
                                                       float* __restrict__ out) {
    __shared__ unsigned       s_mask[NATTR * 3 * 8];  // [attr][val][word]: targets with attr==val
    __shared__ unsigned short s_pairs[PMAX];          // (row_local << 8) | b
    __shared__ int            s_np;
    __shared__ unsigned long long s_target;

    int t = threadIdx.x, w = t >> 5, lane = t & 31;

    // ---- build value-indexed target bitmasks (one ballot set per warp) ----
    {
        int av[NATTR];
        const int* a = tattr + t * NATTR;
        #pragma unroll
        for (int i = 0; i < NATTR; i++) av[i] = a[i];
        #pragma unroll
        for (int ai = 0; ai < NATTR; ai++) {
            #pragma unroll
            for (int v = 0; v < 3; v++) {
                unsigned m = __ballot_sync(0xffffffffu, av[ai] == v);
                if (lane == 0) s_mask[(ai * 3 + v) * 8 + w] = m;
            }
        }
    }
    if (t == 0) s_np = 0;
    __syncthreads();

    int base = blockIdx.x * RPB;
    int q = lane >> 3, oct = lane & 7;      // lane -> (row-in-quad, target-word)

    // ---- phase A: each warp tests 4 rows per iteration (bit-sliced, no ballots) ----
    for (int r0 = w * 4; r0 < RPB; r0 += 32) {
        int rl = r0 + q;                    // row local to block
        int n = base + rl;
        bool rowok = (rl < RPB) && (n < NTRAIN);
        // coalesced 128B load: 4 rows x 8 attrs
        int val = rowok ? attr[(size_t)n * NATTR + oct] : 0;

        // pack row attrs within each octet (all 8 lanes of octet end with full p)
        unsigned p = ((unsigned)val & 3u) << (2 * oct);
        p |= __shfl_xor_sync(0xffffffffu, p, 1);
        p |= __shfl_xor_sync(0xffffffffu, p, 2);
        p |= __shfl_xor_sync(0xffffffffu, p, 4);

        // bit-sliced mismatch count over this lane's 32 targets
        unsigned seen = 0, two = 0;
        #pragma unroll
        for (int ai = 0; ai < NATTR; ai++) {
            unsigned v = (p >> (2 * ai)) & 3u;
            unsigned m = ~s_mask[(ai * 3 + v) * 8 + oct];   // mismatching targets
            two  |= seen & m;
            seen |= m;
        }
        unsigned hit = rowok ? ~two : 0u;   // <=1 mismatch <=> match_score >= 7

        // warp compaction of hit bits into the block pair list
        int c = __popc(hit);
        int pre = c;
        #pragma unroll
        for (int o = 1; o < 32; o <<= 1) {
            int u = __shfl_up_sync(0xffffffffu, pre, o);
            if (lane >= o) pre += u;
        }
        int tot = __shfl_sync(0xffffffffu, pre, 31);
        if (tot) {
            int bpos = 0;
            if (lane == 31) bpos = atomicAdd(&s_np, tot);
            bpos = __shfl_sync(0xffffffffu, bpos, 31);
            int idx = bpos + pre - c;
            unsigned rem = hit;
            while (rem) {
                int bit = __ffs(rem) - 1;
                rem &= rem - 1;
                if (idx < PMAX)
                    s_pairs[idx] = (unsigned short)((rl << 8) | (oct * 32 + bit));
                idx++;
            }
        }
    }
    __syncthreads();
    int np = s_np < PMAX ? s_np : PMAX;

    // ---- phase B: pairs distributed across all 8 warps (8 indep LDG.128 each) ----
    for (int j = w; j < np; j += 8) {
        int pr  = s_pairs[j];
        int row = base + (pr >> 8);
        int b   = pr & 255;

        const float4* rr = (const float4*)(emb + (size_t)row * D);
        const float4* zr = (const float4*)(z + (size_t)b * D);
        float4 r0 = rr[lane];      float4 z0 = zr[lane];
        float4 r1 = rr[lane + 32]; float4 z1 = zr[lane + 32];
        float4 r2 = rr[lane + 64]; float4 z2 = zr[lane + 64];
        float4 r3 = rr[lane + 96]; float4 z3 = zr[lane + 96];

        float ss = r0.x*r0.x + r0.y*r0.y + r0.z*r0.z + r0.w*r0.w
                 + r1.x*r1.x + r1.y*r1.y + r1.z*r1.z + r1.w*r1.w
                 + r2.x*r2.x + r2.y*r2.y + r2.z*r2.z + r2.w*r2.w
                 + r3.x*r3.x + r3.y*r3.y + r3.z*r3.z + r3.w*r3.w;
        float d  = r0.x*z0.x + r0.y*z0.y + r0.z*z0.z + r0.w*z0.w
                 + r1.x*z1.x + r1.y*z1.y + r1.z*z1.z + r1.w*z1.w
                 + r2.x*z2.x + r2.y*z2.y + r2.z*z2.z + r2.w*z2.w
                 + r3.x*z3.x + r3.y*z3.y + r3.z*z3.z + r3.w*z3.w;
        #pragma unroll
        for (int o = 16; o; o >>= 1) {
            ss += __shfl_xor_sync(0xffffffffu, ss, o);
            d  += __shfl_xor_sync(0xffffffffu, d,  o);
        }
        if (lane == 0) {
            float inv = 1.0f / fmaxf(sqrtf(ss), 1e-12f);  // row inv-norm (F.normalize eps)
            int pos = atomicAdd(&g_count[b], 1);
            if (pos < CAP) g_sims[(size_t)b * CAP + pos] = d * inv;
        }
    }

    // ---- release: every thread fences, then one bump of the monotonic counter ----
    __threadfence();
    __syncthreads();
    if (t == 0) {
        unsigned long long my = atomicAdd(&g_done, 1ULL);
        s_target = (my / NBLK_M + 1ULL) * NBLK_M;      // this execution's completion value
    }
    __syncthreads();
    if (blockIdx.x >= TAILB) return;                   // 560 blocks drain; 32 spin

    // ---- spin until all 592 blocks of THIS execution bumped (replay-safe) ----
    if (t == 0) {
        while (*(volatile unsigned long long*)&g_done < s_target) { __nanosleep(128); }
    }
    __syncthreads();
    __threadfence();                                   // acquire all blocks' writes

    // ---- tail: warp-per-query register top-5 (256 warps chip-wide) ----
    int b = blockIdx.x * 8 + w;

    // inv-norm of z[b] (L2-hot); invz > 0 preserves top-k order, applied at end
    const float4* zr = (const float4*)(z + (size_t)b * D);
    float4 z0 = zr[lane], z1 = zr[lane + 32], z2 = zr[lane + 64], z3 = zr[lane + 96];
    float ssz = z0.x*z0.x + z0.y*z0.y + z0.z*z0.z + z0.w*z0.w
              + z1.x*z1.x + z1.y*z1.y + z1.z*z1.z + z1.w*z1.w
              + z2.x*z2.x + z2.y*z2.y + z2.z*z2.z + z2.w*z2.w
              + z3.x*z3.x + z3.y*z3.y + z3.z*z3.z + z3.w*z3.w;
    #pragma unroll
    for (int o = 16; o; o >>= 1) ssz += __shfl_xor_sync(0xffffffffu, ssz, o);
    float invz = 1.0f / fmaxf(sqrtf(ssz), 1e-12f);

    int cnt = __ldcg(&g_count[b]);
    if (cnt > CAP) cnt = CAP;
    if (lane == 0) g_count[b] = 0;                     // reset for next graph replay

    // per-lane sorted top-5 registers over strided sims (bypass L1: other SMs wrote)
    float t0 = -1e30f, t1 = -1e30f, t2 = -1e30f, t3 = -1e30f, t4 = -1e30f;
    for (int i = lane; i < cnt; i += 32) {
        float v = __ldcg(&g_sims[(size_t)b * CAP + i]);
        if (v > t4) {
            if      (v > t0) { t4=t3; t3=t2; t2=t1; t1=t0; t0=v; }
            else if (v > t1) { t4=t3; t3=t2; t2=t1; t1=v; }
            else if (v > t2) { t4=t3; t3=t2; t2=v; }
            else if (v > t3) { t4=t3; t3=v; }
            else             { t4=v; }
        }
    }

    // 5 merge rounds, descending order -> deterministic; zeros clamp each pick at 0
    float sum5 = 0.0f;
    #pragma unroll
    for (int k = 0; k < KNB; k++) {
        float m = t0;
        #pragma unroll
        for (int o = 16; o; o >>= 1) m = fmaxf(m, __shfl_xor_sync(0xffffffffu, m, o));
        sum5 += fmaxf(m, 0.0f);
        unsigned msk = __ballot_sync(0xffffffffu, t0 == m);
        int owner = (int)__ffs(msk) - 1;
        if (lane == owner) { t0=t1; t1=t2; t2=t3; t3=t4; t4=-1e30f; }
    }

    if (lane == 0) {
        float per = 1.0f - (invz * sum5) / (float)KNB;
        g_loss[b] = (cnt >= KNB) ? per : 0.0f;
    }

    // ---- final: last tail block sums g_loss in fixed order (deterministic) ----
    __threadfence();
    __syncthreads();
    if (w == 0) {
        int last = 0;
        if (lane == 0) {
            unsigned long long my2 = atomicAdd(&g_done2, 1ULL);
            last = ((my2 % TAILB) == TAILB - 1) ? 1 : 0;
        }
        last = __shfl_sync(0xffffffffu, last, 0);
        if (last) {
            __threadfence();
            float s = 0.0f;
            #pragma unroll
            for (int i = 0; i < BQ / 32; i++)          // fixed order: deterministic
                s += __ldcg(&g_loss[lane + i * 32]);
            #pragma unroll
            for (int o = 16; o; o >>= 1) s += __shfl_xor_sync(0xffffffffu, s, o);
            if (lane == 0) out[0] = s / (float)BQ;
        }
    }
}

extern "C" void kernel_launch(void* const* d_in, const int* in_sizes, int n_in,
                              void* d_out, int out_size) {
    const float* z     = (const float*)d_in[0];   // z_flowed         [256,512]   f32
    const int*   tattr = (const int*)d_in[1];     // target_attrs     [256,8]     i32
    const float* emb   = (const float*)d_in[2];   // train_embeddings [50000,512] f32
    const int*   attr  = (const int*)d_in[3];     // train_attributes [50000,8]   i32
    float*       out   = (float*)d_out;

    fused_kernel<<<NBLK_M, 256>>>(emb, attr, z, tattr, out);
}

// round 14
// speedup vs baseline: 2.8886x; 1.0063x over previous
#include <cuda_runtime.h>
#include <math.h>

#define BQ      256      // batch (queries)
#define D       512      // embedding dim
#define NTRAIN  50000    // train rows
#define NATTR   8        // attributes
#define CAP     1024     // per-b matched-sim buffer (mean ~130, huge margin)
#define KNB     5        // top-k
#define NBLK_M  592      // 4 blocks/SM x 148 SMs = EXACTLY one wave
#define RPB     85       // rows per block (592*85 = 50320 >= 50000)
#define PMAX    384      // block pair-list cap (mean ~56, +26 sigma margin)
#define TAILB   32       // tail blocks: 32 x 8 warps = 256 queries, one warp each

// ---------------- device scratch (no allocations allowed) ----------------
// g_count zero at static init; tail re-zeroes after reading -> graph-replay-safe.
__device__ int                g_count[BQ];      // matched count per query
__device__ float              g_sims[BQ * CAP]; // matched (dot * inv_row) per query
__device__ float              g_loss[BQ];       // per-query loss contribution
__device__ unsigned long long g_done;           // monotonic match-completion counter
__device__ unsigned long long g_done2;          // monotonic tail-completion counter

__global__ void __launch_bounds__(256, 4) fused_kernel(const float* __restrict__ emb,
                                                       const int* __restrict__ attr,
                                                       const float* __restrict__ z,
                                                       const int* __restrict__ tattr,
                                                       float* __restrict__ out) {
    __shared__ unsigned       s_mask[NATTR * 3 * 8];  // [attr][val][word]: targets with attr==val
    __shared__ unsigned short s_pairs[PMAX];          // (row_local << 8) | b
    __shared__ int            s_np;
    __shared__ unsigned long long s_target;

    int t = threadIdx.x, w = t >> 5, lane = t & 31;

    // ---- build value-indexed target bitmasks (one ballot set per warp) ----
    {
        int av[NATTR];
        const int* a = tattr + t * NATTR;
        #pragma unroll
        for (int i = 0; i < NATTR; i++) av[i] = a[i];
        #pragma unroll
        for (int ai = 0; ai < NATTR; ai++) {
            #pragma unroll
            for (int v = 0; v < 3; v++) {
                unsigned m = __ballot_sync(0xffffffffu, av[ai] == v);
                if (lane == 0) s_mask[(ai * 3 + v) * 8 + w] = m;
            }
        }
    }
    if (t == 0) s_np = 0;
    __syncthreads();

    int base = blockIdx.x * RPB;
    int q = lane >> 3, oct = lane & 7;      // lane -> (row-in-quad, target-word)

    // ---- phase A: each warp tests 4 rows per iteration (bit-sliced, no ballots) ----
    for (int r0 = w * 4; r0 < RPB; r0 += 32) {
        int rl = r0 + q;                    // row local to block
        int n = base + rl;
        bool rowok = (rl < RPB) && (n < NTRAIN);
        // coalesced 128B load: 4 rows x 8 attrs
        int val = rowok ? attr[(size_t)n * NATTR + oct] : 0;

        // pack row attrs within each octet (all 8 lanes of octet end with full p)
        unsigned p = ((unsigned)val & 3u) << (2 * oct);
        p |= __shfl_xor_sync(0xffffffffu, p, 1);
        p |= __shfl_xor_sync(0xffffffffu, p, 2);
        p |= __shfl_xor_sync(0xffffffffu, p, 4);

        // bit-sliced mismatch count over this lane's 32 targets
        unsigned seen = 0, two = 0;
        #pragma unroll
        for (int ai = 0; ai < NATTR; ai++) {
            unsigned v = (p >> (2 * ai)) & 3u;
            unsigned m = ~s_mask[(ai * 3 + v) * 8 + oct];   // mismatching targets
            two  |= seen & m;
            seen |= m;
        }
        unsigned hit = rowok ? ~two : 0u;   // <=1 mismatch <=> match_score >= 7

        // warp compaction of hit bits into the block pair list
        int c = __popc(hit);
        int pre = c;
        #pragma unroll
        for (int o = 1; o < 32; o <<= 1) {
            int u = __shfl_up_sync(0xffffffffu, pre, o);
            if (lane >= o) pre += u;
        }
        int tot = __shfl_sync(0xffffffffu, pre, 31);
        if (tot) {
            int bpos = 0;
            if (lane == 31) bpos = atomicAdd(&s_np, tot);
            bpos = __shfl_sync(0xffffffffu, bpos, 31);
            int idx = bpos + pre - c;
            unsigned rem = hit;
            while (rem) {
                int bit = __ffs(rem) - 1;
                rem &= rem - 1;
                if (idx < PMAX)
                    s_pairs[idx] = (unsigned short)((rl << 8) | (oct * 32 + bit));
                idx++;
            }
        }
    }
    __syncthreads();
    int np = s_np < PMAX ? s_np : PMAX;

    // ---- phase B: pairs distributed across all 8 warps (8 indep LDG.128 each) ----
    for (int j = w; j < np; j += 8) {
        int pr  = s_pairs[j];
        int row = base + (pr >> 8);
        int b   = pr & 255;

        const float4* rr = (const float4*)(emb + (size_t)row * D);
        const float4* zr = (const float4*)(z + (size_t)b * D);
        float4 r0 = rr[lane];      float4 z0 = zr[lane];
        float4 r1 = rr[lane + 32]; float4 z1 = zr[lane + 32];
        float4 r2 = rr[lane + 64]; float4 z2 = zr[lane + 64];
        float4 r3 = rr[lane + 96]; float4 z3 = zr[lane + 96];

        float ss = r0.x*r0.x + r0.y*r0.y + r0.z*r0.z + r0.w*r0.w
                 + r1.x*r1.x + r1.y*r1.y + r1.z*r1.z + r1.w*r1.w
                 + r2.x*r2.x + r2.y*r2.y + r2.z*r2.z + r2.w*r2.w
                 + r3.x*r3.x + r3.y*r3.y + r3.z*r3.z + r3.w*r3.w;
        float d  = r0.x*z0.x + r0.y*z0.y + r0.z*z0.z + r0.w*z0.w
                 + r1.x*z1.x + r1.y*z1.y + r1.z*z1.z + r1.w*z1.w
                 + r2.x*z2.x + r2.y*z2.y + r2.z*z2.z + r2.w*z2.w
                 + r3.x*z3.x + r3.y*z3.y + r3.z*z3.z + r3.w*z3.w;
        #pragma unroll
        for (int o = 16; o; o >>= 1) {
            ss += __shfl_xor_sync(0xffffffffu, ss, o);
            d  += __shfl_xor_sync(0xffffffffu, d,  o);
        }
        if (lane == 0) {
            float inv = 1.0f / fmaxf(sqrtf(ss), 1e-12f);  // row inv-norm (F.normalize eps)
            int pos = atomicAdd(&g_count[b], 1);
            if (pos < CAP) g_sims[(size_t)b * CAP + pos] = d * inv;
        }
    }

    // ---- release: every thread fences, then one bump of the monotonic counter ----
    __threadfence();
    __syncthreads();
    if (t == 0) {
        unsigned long long my = atomicAdd(&g_done, 1ULL);
        s_target = (my / NBLK_M + 1ULL) * NBLK_M;      // this execution's completion value
    }
    __syncthreads();
    if (blockIdx.x >= TAILB) return;                   // 560 blocks drain; 32 spin

    // ---- spin until all 592 blocks of THIS execution bumped (replay-safe) ----
    if (t == 0) {
        while (*(volatile unsigned long long*)&g_done < s_target) { __nanosleep(128); }
    }
    __syncthreads();
    __threadfence();                                   // acquire all blocks' writes

    // ---- tail: warp-per-query register top-5 (256 warps chip-wide) ----
    int b = blockIdx.x * 8 + w;

    // inv-norm of z[b] (L2-hot); invz > 0 preserves top-k order, applied at end
    const float4* zr = (const float4*)(z + (size_t)b * D);
    float4 z0 = zr[lane], z1 = zr[lane + 32], z2 = zr[lane + 64], z3 = zr[lane + 96];
    float ssz = z0.x*z0.x + z0.y*z0.y + z0.z*z0.z + z0.w*z0.w
              + z1.x*z1.x + z1.y*z1.y + z1.z*z1.z + z1.w*z1.w
              + z2.x*z2.x + z2.y*z2.y + z2.z*z2.z + z2.w*z2.w
              + z3.x*z3.x + z3.y*z3.y + z3.z*z3.z + z3.w*z3.w;
    #pragma unroll
    for (int o = 16; o; o >>= 1) ssz += __shfl_xor_sync(0xffffffffu, ssz, o);
    float invz = 1.0f / fmaxf(sqrtf(ssz), 1e-12f);

    int cnt = __ldcg(&g_count[b]);
    if (cnt > CAP) cnt = CAP;
    if (lane == 0) g_count[b] = 0;                     // reset for next graph replay

    // per-lane sorted top-5 registers over strided sims (bypass L1: other SMs wrote)
    float t0 = -1e30f, t1 = -1e30f, t2 = -1e30f, t3 = -1e30f, t4 = -1e30f;
    for (int i = lane; i < cnt; i += 32) {
        float v = __ldcg(&g_sims[(size_t)b * CAP + i]);
        if (v > t4) {
            if      (v > t0) { t4=t3; t3=t2; t2=t1; t1=t0; t0=v; }
            else if (v > t1) { t4=t3; t3=t2; t2=t1; t1=v; }
            else if (v > t2) { t4=t3; t3=t2; t2=v; }
            else if (v > t3) { t4=t3; t3=v; }
            else             { t4=v; }
        }
    }

    // 5 merge rounds, descending order -> deterministic; zeros clamp each pick at 0
    float sum5 = 0.0f;
    #pragma unroll
    for (int k = 0; k < KNB; k++) {
        float m = t0;
        #pragma unroll
        for (int o = 16; o; o >>= 1) m = fmaxf(m, __shfl_xor_sync(0xffffffffu, m, o));
        sum5 += fmaxf(m, 0.0f);
        unsigned msk = __ballot_sync(0xffffffffu, t0 == m);
        int owner = (int)__ffs(msk) - 1;
        if (lane == owner) { t0=t1; t1=t2; t2=t3; t3=t4; t4=-1e30f; }
    }

    if (lane == 0) {
        float per = 1.0f - (invz * sum5) / (float)KNB;
        g_loss[b] = (cnt >= KNB) ? per : 0.0f;
    }

    // ---- final: last tail block sums g_loss in fixed order (deterministic) ----
    __threadfence();
    __syncthreads();
    if (w == 0) {
        int last = 0;
        if (lane == 0) {
            unsigned long long my2 = atomicAdd(&g_done2, 1ULL);
            last = ((my2 % TAILB) == TAILB - 1) ? 1 : 0;
        }
        last = __shfl_sync(0xffffffffu, last, 0);
        if (last) {
            __threadfence();
            float s = 0.0f;
            #pragma unroll
            for (int i = 0; i < BQ / 32; i++)          // fixed order: deterministic
                s += __ldcg(&g_loss[lane + i * 32]);
            #pragma unroll
            for (int o = 16; o; o >>= 1) s += __shfl_xor_sync(0xffffffffu, s, o);
            if (lane == 0) out[0] = s / (float)BQ;
        }
    }
}

extern "C" void kernel_launch(void* const* d_in, const int* in_sizes, int n_in,
                              void* d_out, int out_size) {
    const float* z     = (const float*)d_in[0];   // z_flowed         [256,512]   f32
    const int*   tattr = (const int*)d_in[1];     // target_attrs     [256,8]     i32
    const float* emb   = (const float*)d_in[2];   // train_embeddings [50000,512] f32
    const int*   attr  = (const int*)d_in[3];     // train_attributes [50000,8]   i32
    float*       out   = (float*)d_out;

    fused_kernel<<<NBLK_M, 256>>>(emb, attr, z, tattr, out);
}

// round 15
// speedup vs baseline: 3.4513x; 1.1948x over previous
#include <cuda_runtime.h>
#include <math.h>

#define BQ      256      // batch (queries)
#define D       512      // embedding dim
#define NTRAIN  50000    // train rows
#define NATTR   8        // attributes
#define CAP     1024     // per-b matched-sim buffer (mean ~130, huge margin)
#define KNB     5        // top-k
#define NBLK_M  592      // 4 blocks/SM x 148 SMs = one co-resident wave
#define CHUNK   32       // rows grabbed per work-steal (8 warps x 4 rows)
#define PCHUNK  128      // per-chunk pair list cap (mean ~21, astronomically safe)
#define TAILB   32       // tail blocks: 32 x 8 warps = 256 queries, one warp each

// ---------------- device scratch (no allocations allowed) ----------------
// g_count / g_rows are reset by the final block each execution -> graph-replay-safe.
__device__ int                g_rows;           // work-steal row cursor (reset each exec)
__device__ int                g_count[BQ];      // matched count per query
__device__ float              g_sims[BQ * CAP]; // matched (dot * inv_row) per query
__device__ float              g_loss[BQ];       // per-query loss contribution
__device__ unsigned long long g_done;           // monotonic match-completion counter
__device__ unsigned long long g_done2;          // monotonic tail-completion counter

__global__ void __launch_bounds__(256, 4) fused_kernel(const float* __restrict__ emb,
                                                       const int* __restrict__ attr,
                                                       const float* __restrict__ z,
                                                       const int* __restrict__ tattr,
                                                       float* __restrict__ out) {
    __shared__ unsigned       s_mask[NATTR * 3 * 8];  // [attr][val][word]: targets with attr==val
    __shared__ int            s_pairs[PCHUNK];        // row*256 + b (global row)
    __shared__ int            s_np;
    __shared__ int            s_start;
    __shared__ unsigned long long s_target;

    int t = threadIdx.x, w = t >> 5, lane = t & 31;

    // ---- build value-indexed target bitmasks (one ballot set per warp) ----
    {
        int av[NATTR];
        const int* a = tattr + t * NATTR;
        #pragma unroll
        for (int i = 0; i < NATTR; i++) av[i] = a[i];
        #pragma unroll
        for (int ai = 0; ai < NATTR; ai++) {
            #pragma unroll
            for (int v = 0; v < 3; v++) {
                unsigned m = __ballot_sync(0xffffffffu, av[ai] == v);
                if (lane == 0) s_mask[(ai * 3 + v) * 8 + w] = m;
            }
        }
    }
    __syncthreads();

    int q = lane >> 3, oct = lane & 7;      // lane -> (row-in-quad, target-word)

    // ================= work-stealing match loop =================
    while (true) {
        if (t == 0) { s_start = atomicAdd(&g_rows, CHUNK); s_np = 0; }
        __syncthreads();
        int start = s_start;
        if (start >= NTRAIN) break;

        // ---- phase A: one bit-sliced iteration (8 warps x 4 rows = 32 rows) ----
        int n = start + w * 4 + q;
        bool rowok = (n < NTRAIN);
        int val = rowok ? attr[(size_t)n * NATTR + oct] : 0;   // coalesced 128B per quad

        // pack row attrs within each octet (all 8 lanes of octet end with full p)
        unsigned p = ((unsigned)val & 3u) << (2 * oct);
        p |= __shfl_xor_sync(0xffffffffu, p, 1);
        p |= __shfl_xor_sync(0xffffffffu, p, 2);
        p |= __shfl_xor_sync(0xffffffffu, p, 4);

        // bit-sliced mismatch count over this lane's 32 targets
        unsigned seen = 0, two = 0;
        #pragma unroll
        for (int ai = 0; ai < NATTR; ai++) {
            unsigned v = (p >> (2 * ai)) & 3u;
            unsigned m = ~s_mask[(ai * 3 + v) * 8 + oct];     // mismatching targets
            two  |= seen & m;
            seen |= m;
        }
        unsigned hit = rowok ? ~two : 0u;   // <=1 mismatch <=> match_score >= 7

        // warp compaction of hit bits into the chunk pair list
        int c = __popc(hit);
        int pre = c;
        #pragma unroll
        for (int o = 1; o < 32; o <<= 1) {
            int u = __shfl_up_sync(0xffffffffu, pre, o);
            if (lane >= o) pre += u;
        }
        int tot = __shfl_sync(0xffffffffu, pre, 31);
        if (tot) {
            int bpos = 0;
            if (lane == 31) bpos = atomicAdd(&s_np, tot);
            bpos = __shfl_sync(0xffffffffu, bpos, 31);
            int idx = bpos + pre - c;
            unsigned rem = hit;
            while (rem) {
                int bit = __ffs(rem) - 1;
                rem &= rem - 1;
                if (idx < PCHUNK)
                    s_pairs[idx] = n * 256 + (oct * 32 + bit);
                idx++;
            }
        }
        __syncthreads();
        int np = s_np < PCHUNK ? s_np : PCHUNK;

        // ---- phase B: this chunk's pairs across all 8 warps (8 indep LDG.128 each) ----
        for (int j = w; j < np; j += 8) {
            int pr  = s_pairs[j];
            int row = pr >> 8;
            int b   = pr & 255;

            const float4* rr = (const float4*)(emb + (size_t)row * D);
            const float4* zr = (const float4*)(z + (size_t)b * D);
            float4 r0 = rr[lane];      float4 z0 = zr[lane];
            float4 r1 = rr[lane + 32]; float4 z1 = zr[lane + 32];
            float4 r2 = rr[lane + 64]; float4 z2 = zr[lane + 64];
            float4 r3 = rr[lane + 96]; float4 z3 = zr[lane + 96];

            float ss = r0.x*r0.x + r0.y*r0.y + r0.z*r0.z + r0.w*r0.w
                     + r1.x*r1.x + r1.y*r1.y + r1.z*r1.z + r1.w*r1.w
                     + r2.x*r2.x + r2.y*r2.y + r2.z*r2.z + r2.w*r2.w
                     + r3.x*r3.x + r3.y*r3.y + r3.z*r3.z + r3.w*r3.w;
            float d  = r0.x*z0.x + r0.y*z0.y + r0.z*z0.z + r0.w*z0.w
                     + r1.x*z1.x + r1.y*z1.y + r1.z*z1.z + r1.w*z1.w
                     + r2.x*z2.x + r2.y*z2.y + r2.z*z2.z + r2.w*z2.w
                     + r3.x*z3.x + r3.y*z3.y + r3.z*z3.z + r3.w*z3.w;
            #pragma unroll
            for (int o = 16; o; o >>= 1) {
                ss += __shfl_xor_sync(0xffffffffu, ss, o);
                d  += __shfl_xor_sync(0xffffffffu, d,  o);
            }
            if (lane == 0) {
                float inv = 1.0f / fmaxf(sqrtf(ss), 1e-12f);  // row inv-norm (F.normalize eps)
                int pos = atomicAdd(&g_count[b], 1);
                if (pos < CAP) g_sims[(size_t)b * CAP + pos] = d * inv;
            }
        }
        __syncthreads();
    }

    // ---- release: fence, then one bump of the monotonic completion counter ----
    __threadfence();
    __syncthreads();
    if (t == 0) {
        unsigned long long my = atomicAdd(&g_done, 1ULL);
        s_target = (my / NBLK_M + 1ULL) * NBLK_M;      // this execution's completion value
    }
    __syncthreads();
    if (blockIdx.x >= TAILB) return;                   // 560 blocks drain; 32 spin

    // ---- spin until all 592 blocks of THIS execution bumped (replay-safe) ----
    if (t == 0) {
        while (*(volatile unsigned long long*)&g_done < s_target) { __nanosleep(128); }
    }
    __syncthreads();
    __threadfence();                                   // acquire all blocks' writes

    // ---- tail: warp-per-query register top-5 (256 warps chip-wide) ----
    int b = blockIdx.x * 8 + w;

    // inv-norm of z[b] (L2-hot); invz > 0 preserves top-k order, applied at end
    const float4* zr = (const float4*)(z + (size_t)b * D);
    float4 z0 = zr[lane], z1 = zr[lane + 32], z2 = zr[lane + 64], z3 = zr[lane + 96];
    float ssz = z0.x*z0.x + z0.y*z0.y + z0.z*z0.z + z0.w*z0.w
              + z1.x*z1.x + z1.y*z1.y + z1.z*z1.z + z1.w*z1.w
              + z2.x*z2.x + z2.y*z2.y + z2.z*z2.z + z2.w*z2.w
              + z3.x*z3.x + z3.y*z3.y + z3.z*z3.z + z3.w*z3.w;
    #pragma unroll
    for (int o = 16; o; o >>= 1) ssz += __shfl_xor_sync(0xffffffffu, ssz, o);
    float invz = 1.0f / fmaxf(sqrtf(ssz), 1e-12f);

    int cnt = __ldcg(&g_count[b]);
    if (cnt > CAP) cnt = CAP;
    if (lane == 0) g_count[b] = 0;                     // reset for next graph replay

    // per-lane sorted top-5 registers over strided sims (bypass L1: other SMs wrote)
    float t0 = -1e30f, t1 = -1e30f, t2 = -1e30f, t3 = -1e30f, t4 = -1e30f;
    for (int i = lane; i < cnt; i += 32) {
        float v = __ldcg(&g_sims[(size_t)b * CAP + i]);
        if (v > t4) {
            if      (v > t0) { t4=t3; t3=t2; t2=t1; t1=t0; t0=v; }
            else if (v > t1) { t4=t3; t3=t2; t2=t1; t1=v; }
            else if (v > t2) { t4=t3; t3=t2; t2=v; }
            else if (v > t3) { t4=t3; t3=v; }
            else             { t4=v; }
        }
    }

    // 5 merge rounds, descending order -> deterministic; zeros clamp each pick at 0
    float sum5 = 0.0f;
    #pragma unroll
    for (int k = 0; k < KNB; k++) {
        float m = t0;
        #pragma unroll
        for (int o = 16; o; o >>= 1) m = fmaxf(m, __shfl_xor_sync(0xffffffffu, m, o));
        sum5 += fmaxf(m, 0.0f);
        unsigned msk = __ballot_sync(0xffffffffu, t0 == m);
        int owner = (int)__ffs(msk) - 1;
        if (lane == owner) { t0=t1; t1=t2; t2=t3; t3=t4; t4=-1e30f; }
    }

    if (lane == 0) {
        float per = 1.0f - (invz * sum5) / (float)KNB;
        g_loss[b] = (cnt >= KNB) ? per : 0.0f;
    }

    // ---- final: last tail block sums g_loss in fixed order (deterministic) ----
    __threadfence();
    __syncthreads();
    if (w == 0) {
        int last = 0;
        if (lane == 0) {
            unsigned long long my2 = atomicAdd(&g_done2, 1ULL);
            last = ((my2 % TAILB) == TAILB - 1) ? 1 : 0;
        }
        last = __shfl_sync(0xffffffffu, last, 0);
        if (last) {
            __threadfence();
            float s = 0.0f;
            #pragma unroll
            for (int i = 0; i < BQ / 32; i++)          // fixed order: deterministic
                s += __ldcg(&g_loss[lane + i * 32]);
            #pragma unroll
            for (int o = 16; o; o >>= 1) s += __shfl_xor_sync(0xffffffffu, s, o);
            if (lane == 0) {
                out[0] = s / (float)BQ;
                g_rows = 0;                            // reset work cursor for next replay
            }
        }
    }
}

extern "C" void kernel_launch(void* const* d_in, const int* in_sizes, int n_in,
                              void* d_out, int out_size) {
    const float* z     = (const float*)d_in[0];   // z_flowed         [256,512]   f32
    const int*   tattr = (const int*)d_in[1];     // target_attrs     [256,8]     i32
    const float* emb   = (const float*)d_in[2];   // train_embeddings [50000,512] f32
    const int*   attr  = (const int*)d_in[3];     // train_attributes [50000,8]   i32
    float*       out   = (float*)d_out;

    fused_kernel<<<NBLK_M, 256>>>(emb, attr, z, tattr, out);
}

// round 17
// speedup vs baseline: 3.4701x; 1.0054x over previous
#include <cuda_runtime.h>
#include <math.h>

#define BQ      256      // batch (queries)
#define D       512      // embedding dim
#define NTRAIN  50000    // train rows
#define NATTR   8        // attributes
#define CAP     1024     // per-b matched-sim buffer (mean ~130, huge margin)
#define KNB     5        // top-k
#define NBLK_M  592      // 4 blocks/SM x 148 SMs = one co-resident wave
#define CHUNK   32       // rows grabbed per work-steal (8 warps x 4 rows)
#define PCHUNK  128      // per-chunk pair list cap (mean ~21, astronomically safe)
#define TAILB   32       // tail blocks: 32 x 8 warps = 256 queries, one warp each

// ---------------- device scratch (no allocations allowed) ----------------
// g_count / g_rows are reset by the final block each execution -> graph-replay-safe.
__device__ int                g_rows;           // work-steal row cursor (reset each exec)
__device__ int                g_count[BQ];      // matched count per query
__device__ float              g_sims[BQ * CAP]; // matched (dot * inv_row) per query
__device__ float              g_loss[BQ];       // per-query loss contribution
__device__ unsigned long long g_done;           // monotonic match-completion counter
__device__ unsigned long long g_done2;          // monotonic tail-completion counter

__global__ void __launch_bounds__(256, 4) fused_kernel(const float* __restrict__ emb,
                                                       const int* __restrict__ attr,
                                                       const float* __restrict__ z,
                                                       const int* __restrict__ tattr,
                                                       float* __restrict__ out) {
    __shared__ unsigned       s_mask[NATTR * 3 * 8];  // [attr][val][word]: targets with attr==val
    __shared__ int            s_pairs[PCHUNK];        // row*256 + b (global row)
    __shared__ int            s_np;
    __shared__ int            s_start;
    __shared__ unsigned long long s_target;

    int t = threadIdx.x, w = t >> 5, lane = t & 31;

    // ---- build value-indexed target bitmasks (one ballot set per warp) ----
    {
        int av[NATTR];
        const int* a = tattr + t * NATTR;
        #pragma unroll
        for (int i = 0; i < NATTR; i++) av[i] = a[i];
        #pragma unroll
        for (int ai = 0; ai < NATTR; ai++) {
            #pragma unroll
            for (int v = 0; v < 3; v++) {
                unsigned m = __ballot_sync(0xffffffffu, av[ai] == v);
                if (lane == 0) s_mask[(ai * 3 + v) * 8 + w] = m;
            }
        }
    }
    __syncthreads();

    int q = lane >> 3, oct = lane & 7;      // phase A: lane -> (row-in-quad, target-word)
    int po = lane >> 3, lo = lane & 7;      // phase B: lane -> (pair-octet, lane-in-octet)

    // ================= work-stealing match loop =================
    while (true) {
        if (t == 0) { s_start = atomicAdd(&g_rows, CHUNK); s_np = 0; }
        __syncthreads();
        int start = s_start;
        if (start >= NTRAIN) break;

        // ---- phase A: one bit-sliced iteration (8 warps x 4 rows = 32 rows) ----
        int n = start + w * 4 + q;
        bool rowok = (n < NTRAIN);
        int val = rowok ? attr[(size_t)n * NATTR + oct] : 0;   // coalesced 128B per quad

        // pack row attrs within each octet (all 8 lanes of octet end with full p)
        unsigned p = ((unsigned)val & 3u) << (2 * oct);
        p |= __shfl_xor_sync(0xffffffffu, p, 1);
        p |= __shfl_xor_sync(0xffffffffu, p, 2);
        p |= __shfl_xor_sync(0xffffffffu, p, 4);

        // bit-sliced mismatch count over this lane's 32 targets
        unsigned seen = 0, two = 0;
        #pragma unroll
        for (int ai = 0; ai < NATTR; ai++) {
            unsigned v = (p >> (2 * ai)) & 3u;
            unsigned m = ~s_mask[(ai * 3 + v) * 8 + oct];     // mismatching targets
            two  |= seen & m;
            seen |= m;
        }
        unsigned hit = rowok ? ~two : 0u;   // <=1 mismatch <=> match_score >= 7

        // warp compaction of hit bits into the chunk pair list
        int c = __popc(hit);
        int pre = c;
        #pragma unroll
        for (int o = 1; o < 32; o <<= 1) {
            int u = __shfl_up_sync(0xffffffffu, pre, o);
            if (lane >= o) pre += u;
        }
        int tot = __shfl_sync(0xffffffffu, pre, 31);
        if (tot) {
            int bpos = 0;
            if (lane == 31) bpos = atomicAdd(&s_np, tot);
            bpos = __shfl_sync(0xffffffffu, bpos, 31);
            int idx = bpos + pre - c;
            unsigned rem = hit;
            while (rem) {
                int bit = __ffs(rem) - 1;
                rem &= rem - 1;
                if (idx < PCHUNK)
                    s_pairs[idx] = n * 256 + (oct * 32 + bit);
                idx++;
            }
        }
        __syncthreads();
        int np = s_np < PCHUNK ? s_np : PCHUNK;

        // ---- phase B: one pair per OCTET (4 pairs in flight per warp, MLP~32) ----
        for (int jb = w * 4; jb < np; jb += 32) {
            int j = jb + po;
            bool active = (j < np);
            int pr  = s_pairs[active ? j : 0];       // clamp: inactive octets redo pair 0
            int row = pr >> 8;
            int b   = pr & 255;

            // lane lo covers float4 indices lo, lo+8, ..., lo+120 (128B coalesced/octet)
            const float4* rr4 = (const float4*)(emb + (size_t)row * D);
            const float4* zr4 = (const float4*)(z + (size_t)b * D);
            float ss = 0.0f, d = 0.0f;
            #pragma unroll
            for (int i = 0; i < 16; i++) {
                float4 r  = rr4[i * 8 + lo];
                float4 zz = zr4[i * 8 + lo];
                ss += r.x*r.x + r.y*r.y + r.z*r.z + r.w*r.w;
                d  += r.x*zz.x + r.y*zz.y + r.z*zz.z + r.w*zz.w;
            }
            // octet reduction: offsets 1,2,4 stay inside the octet (all 32 lanes execute)
            #pragma unroll
            for (int o = 1; o < 8; o <<= 1) {
                ss += __shfl_xor_sync(0xffffffffu, ss, o);
                d  += __shfl_xor_sync(0xffffffffu, d,  o);
            }
            if (active && lo == 0) {
                float inv = 1.0f / fmaxf(sqrtf(ss), 1e-12f);  // row inv-norm (F.normalize eps)
                int pos = atomicAdd(&g_count[b], 1);
                if (pos < CAP) g_sims[(size_t)b * CAP + pos] = d * inv;
            }
        }
        __syncthreads();
    }

    // ---- release: fence, then one bump of the monotonic completion counter ----
    __threadfence();
    __syncthreads();
    if (t == 0) {
        unsigned long long my = atomicAdd(&g_done, 1ULL);
        s_target = (my / NBLK_M + 1ULL) * NBLK_M;      // this execution's completion value
    }
    __syncthreads();
    if (blockIdx.x >= TAILB) return;                   // 560 blocks drain; 32 spin

    // ---- spin until all 592 blocks of THIS execution bumped (replay-safe) ----
    if (t == 0) {
        while (*(volatile unsigned long long*)&g_done < s_target) { __nanosleep(128); }
    }
    __syncthreads();
    __threadfence();                                   // acquire all blocks' writes

    // ---- tail: warp-per-query register top-5 (256 warps chip-wide) ----
    int b = blockIdx.x * 8 + w;

    // inv-norm of z[b] (L2-hot); invz > 0 preserves top-k order, applied at end
    const float4* zr = (const float4*)(z + (size_t)b * D);
    float4 z0 = zr[lane], z1 = zr[lane + 32], z2 = zr[lane + 64], z3 = zr[lane + 96];
    float ssz = z0.x*z0.x + z0.y*z0.y + z0.z*z0.z + z0.w*z0.w
              + z1.x*z1.x + z1.y*z1.y + z1.z*z1.z + z1.w*z1.w
              + z2.x*z2.x + z2.y*z2.y + z2.z*z2.z + z2.w*z2.w
              + z3.x*z3.x + z3.y*z3.y + z3.z*z3.z + z3.w*z3.w;
    #pragma unroll
    for (int o = 16; o; o >>= 1) ssz += __shfl_xor_sync(0xffffffffu, ssz, o);
    float invz = 1.0f / fmaxf(sqrtf(ssz), 1e-12f);

    int cnt = __ldcg(&g_count[b]);
    if (cnt > CAP) cnt = CAP;
    if (lane == 0) g_count[b] = 0;                     // reset for next graph replay

    // per-lane sorted top-5 registers over strided sims (bypass L1: other SMs wrote)
    float t0 = -1e30f, t1 = -1e30f, t2 = -1e30f, t3 = -1e30f, t4 = -1e30f;
    for (int i = lane; i < cnt; i += 32) {
        float v = __ldcg(&g_sims[(size_t)b * CAP + i]);
        if (v > t4) {
            if      (v > t0) { t4=t3; t3=t2; t2=t1; t1=t0; t0=v; }
            else if (v > t1) { t4=t3; t3=t2; t2=t1; t1=v; }
            else if (v > t2) { t4=t3; t3=t2; t2=v; }
            else if (v > t3) { t4=t3; t3=v; }
            else             { t4=v; }
        }
    }

    // 5 merge rounds, descending order -> deterministic; zeros clamp each pick at 0
    float sum5 = 0.0f;
    #pragma unroll
    for (int k = 0; k < KNB; k++) {
        float m = t0;
        #pragma unroll
        for (int o = 16; o; o >>= 1) m = fmaxf(m, __shfl_xor_sync(0xffffffffu, m, o));
        sum5 += fmaxf(m, 0.0f);
        unsigned msk = __ballot_sync(0xffffffffu, t0 == m);
        int owner = (int)__ffs(msk) - 1;
        if (lane == owner) { t0=t1; t1=t2; t2=t3; t3=t4; t4=-1e30f; }
    }

    if (lane == 0) {
        float per = 1.0f - (invz * sum5) / (float)KNB;
        g_loss[b] = (cnt >= KNB) ? per : 0.0f;
    }

    // ---- final: last tail block sums g_loss in fixed order (deterministic) ----
    __threadfence();
    __syncthreads();
    if (w == 0) {
        int last = 0;
        if (lane == 0) {
            unsigned long long my2 = atomicAdd(&g_done2, 1ULL);
            last = ((my2 % TAILB) == TAILB - 1) ? 1 : 0;
        }
        last = __shfl_sync(0xffffffffu, last, 0);
        if (last) {
            __threadfence();
            float s = 0.0f;
            #pragma unroll
            for (int i = 0; i < BQ / 32; i++)          // fixed order: deterministic
                s += __ldcg(&g_loss[lane + i * 32]);
            #pragma unroll
            for (int o = 16; o; o >>= 1) s += __shfl_xor_sync(0xffffffffu, s, o);
            if (lane == 0) {
                out[0] = s / (float)BQ;
                g_rows = 0;                            // reset work cursor for next replay
            }
        }
    }
}

extern "C" void kernel_launch(void* const* d_in, const int* in_sizes, int n_in,
                              void* d_out, int out_size) {
    const float* z     = (const float*)d_in[0];   // z_flowed         [256,512]   f32
    const int*   tattr = (const int*)d_in[1];     // target_attrs     [256,8]     i32
    const float* emb   = (const float*)d_in[2];   // train_embeddings [50000,512] f32
    const int*   attr  = (const int*)d_in[3];     // train_attributes [50000,8]   i32
    float*       out   = (float*)d_out;

    fused_kernel<<<NBLK_M, 256>>>(emb, attr, z, tattr, out);
}